// round 7
// baseline (speedup 1.0000x reference)
#include <cuda_runtime.h>
#include <cuda_bf16.h>
#include <cstdint>

// Problem constants (fixed by the reference)
#define NN 1024
#define SS 64
#define DD 256
#define HH 4
#define HDIM 64
#define EE 4096
#define MROWS (NN * SS)   // 65536

// ---------------- scratch (device globals; no allocs allowed) ----------------
__device__ __nv_bfloat16 g_xnb[MROWS * DD];     // layernormed features (bf16)
__device__ __nv_bfloat16 g_qkvb[MROWS * 768];   // stacked q|k|v (bf16)
__device__ __nv_bfloat16 g_ctxb[MROWS * DD];    // per-src summed context (bf16)
__device__ __nv_bfloat16 g_wtb[4 * DD * DD];    // stacked weights [n][k]: wq,wk,wv,wo
__device__ float g_bqkv[768];                   // stacked biases bq|bk|bv
__device__ int g_off[NN + 1];
__device__ int g_adj[EE];
__device__ int g_len[NN];
__device__ int g_step;

// ---------------- mma helpers ----------------
__device__ __forceinline__ void ldsm4(uint32_t* r, uint32_t addr) {
    asm volatile("ldmatrix.sync.aligned.m8n8.x4.shared.b16 {%0,%1,%2,%3}, [%4];\n"
                 : "=r"(r[0]), "=r"(r[1]), "=r"(r[2]), "=r"(r[3]) : "r"(addr));
}

__device__ __forceinline__ void ldsm4t(uint32_t* r, uint32_t addr) {
    asm volatile("ldmatrix.sync.aligned.m8n8.x4.trans.shared.b16 {%0,%1,%2,%3}, [%4];\n"
                 : "=r"(r[0]), "=r"(r[1]), "=r"(r[2]), "=r"(r[3]) : "r"(addr));
}

__device__ __forceinline__ void mma_bf16(float* d, const uint32_t* a, const uint32_t* b) {
    asm volatile(
        "mma.sync.aligned.m16n8k16.row.col.f32.bf16.bf16.f32 "
        "{%0,%1,%2,%3}, {%4,%5,%6,%7}, {%8,%9}, {%0,%1,%2,%3};\n"
        : "+f"(d[0]), "+f"(d[1]), "+f"(d[2]), "+f"(d[3])
        : "r"(a[0]), "r"(a[1]), "r"(a[2]), "r"(a[3]), "r"(b[0]), "r"(b[1]));
}

__device__ __forceinline__ uint32_t packbf(float x, float y) {
    __nv_bfloat162 p = __floats2bfloat162_rn(x, y);
    return *(uint32_t*)&p;
}

#define CP16(dst, src) \
    asm volatile("cp.async.cg.shared.global [%0], [%1], 16;\n" :: "r"(dst), "l"(src))
#define CP_COMMIT() asm volatile("cp.async.commit_group;\n" ::: "memory")
#define CP_WAIT(n)  asm volatile("cp.async.wait_group %0;\n" :: "n"(n) : "memory")

// ---------------- fused graph preprocessing: detect + len + hist + scan -----
__global__ __launch_bounds__(1024) void graph_kernel(const int* __restrict__ ei32,
                                                     const float* __restrict__ masks) {
    __shared__ int s[NN];
    int t = threadIdx.x;

    // dtype detection: int64 edge ids have zero high words
    int nz = 0;
    for (int i = t; i < EE; i += 1024) nz |= (ei32[2 * i + 1] != 0);
    nz = __syncthreads_or(nz);
    int step = nz ? 1 : 2;
    if (t == 0) g_step = step;

    // lengths (prefix masks)
    {
        int c = 0;
        #pragma unroll 8
        for (int q = 0; q < SS; q++) c += (masks[t * SS + q] > 0.0f);
        g_len[t] = c;
    }

    // histogram of src
    s[t] = 0;
    __syncthreads();
    for (int e = t; e < EE; e += 1024) atomicAdd(&s[ei32[step * e]], 1);
    __syncthreads();

    // inclusive scan (Hillis-Steele)
    for (int o = 1; o < NN; o <<= 1) {
        int v = (t >= o) ? s[t - o] : 0;
        __syncthreads();
        s[t] += v;
        __syncthreads();
    }
    g_off[t + 1] = s[t];
    if (t == 0) g_off[0] = 0;
}

__global__ void csr_scatter(const int* __restrict__ ei32) {
    int e = blockIdx.x * blockDim.x + threadIdx.x;
    if (e >= EE) return;
    int step = g_step;
    int src = ei32[step * e];
    int cnt = 0;  // rank among earlier edges with same src -> deterministic
    for (int j = 0; j < e; j++) cnt += (ei32[step * j] == src);
    g_adj[g_off[src] + cnt] = ei32[step * (EE + e)];
}

// ---------------- weights (stacked transpose + bf16) + biases ----------------
__global__ void wtb_kernel(const float* __restrict__ wq, const float* __restrict__ wk,
                           const float* __restrict__ wv, const float* __restrict__ wo,
                           const float* __restrict__ bq, const float* __restrict__ bk,
                           const float* __restrict__ bv) {
    int bx = blockIdx.x;
    if (bx >= 1024) {   // bias blocks
        int i = (bx - 1024) * 256 + threadIdx.x;  // 0..767
        g_bqkv[i] = (i < 256) ? bq[i] : (i < 512) ? bk[i - 256] : bv[i - 512];
        return;
    }
    const float* w = (bx < 256) ? wq : (bx < 512) ? wk : (bx < 768) ? wv : wo;
    int n = bx & 255;
    for (int k = threadIdx.x; k < DD; k += blockDim.x)
        g_wtb[bx * DD + k] = __float2bfloat16(w[k * DD + n]);
}

// ---------------- LayerNorm -> bf16 output ----------------
__global__ __launch_bounds__(256) void ln_kernel(const float* __restrict__ x,
                                                 const float* __restrict__ w,
                                                 const float* __restrict__ b) {
    int warp = (blockIdx.x * blockDim.x + threadIdx.x) >> 5;
    int lane = threadIdx.x & 31;
    if (warp >= MROWS) return;
    const float* xr = x + (size_t)warp * DD + lane * 8;
    float4 a = *(const float4*)xr;
    float4 c = *(const float4*)(xr + 4);
    float s  = a.x + a.y + a.z + a.w + c.x + c.y + c.z + c.w;
    float s2 = a.x*a.x + a.y*a.y + a.z*a.z + a.w*a.w
             + c.x*c.x + c.y*c.y + c.z*c.z + c.w*c.w;
    #pragma unroll
    for (int o = 16; o > 0; o >>= 1) {
        s  += __shfl_xor_sync(0xffffffffu, s,  o);
        s2 += __shfl_xor_sync(0xffffffffu, s2, o);
    }
    float mu  = s * (1.0f / DD);
    float var = s2 * (1.0f / DD) - mu * mu;
    float r = rsqrtf(var + 1e-5f);
    float4 w0 = *(const float4*)(w + lane * 8);
    float4 w1 = *(const float4*)(w + lane * 8 + 4);
    float4 b0 = *(const float4*)(b + lane * 8);
    float4 b1 = *(const float4*)(b + lane * 8 + 4);
    float o0x = (a.x - mu) * r * w0.x + b0.x, o0y = (a.y - mu) * r * w0.y + b0.y;
    float o0z = (a.z - mu) * r * w0.z + b0.z, o0w = (a.w - mu) * r * w0.w + b0.w;
    float o1x = (c.x - mu) * r * w1.x + b1.x, o1y = (c.y - mu) * r * w1.y + b1.y;
    float o1z = (c.z - mu) * r * w1.z + b1.z, o1w = (c.w - mu) * r * w1.w + b1.w;
    uint4 u = make_uint4(packbf(o0x, o0y), packbf(o0z, o0w),
                         packbf(o1x, o1y), packbf(o1z, o1w));
    *(uint4*)(g_xnb + (size_t)warp * DD + lane * 8) = u;
}

// ---------------- full-K bf16 GEMM, chunk-pipelined staging ------------------
// CTA tile 128m x 64n, K=256 staged as 4 cp.async commit groups of K=64;
// compute starts after chunk 0 lands (wait_group 3..0). 8 warps 4Mx2N.
__global__ __launch_bounds__(256) void gemm2(const __nv_bfloat16* __restrict__ A,
                                             const __nv_bfloat16* __restrict__ Wt,
                                             const float* __restrict__ bias,
                                             __nv_bfloat16* __restrict__ Cb, int ldc,
                                             float* __restrict__ Cf,
                                             const float* __restrict__ resid,
                                             const float* __restrict__ mask) {
    extern __shared__ __align__(16) __nv_bfloat16 smem2[];
    __nv_bfloat16* As = smem2;              // [128][264] (stride 528 B)
    __nv_bfloat16* Ws = smem2 + 128 * 264;  // [64][264]

    int tid = threadIdx.x;
    int wid = tid >> 5, lane = tid & 31;
    int m0 = blockIdx.y * 128, n0 = blockIdx.x * 64;
    int wm = (wid & 3) * 32, wn = (wid >> 2) * 32;

    uint32_t asb = (uint32_t)__cvta_generic_to_shared(As);
    uint32_t wsb = (uint32_t)__cvta_generic_to_shared(Ws);

    // stage K in 4 chunks of 64 (128 B per row-chunk), one commit group each
    #pragma unroll
    for (int ch = 0; ch < 4; ch++) {
        #pragma unroll
        for (int i = 0; i < 4; i++) {        // A: 128 rows x 8 segs
            int t = tid + i * 256;
            int r = t >> 3, c = t & 7;
            CP16(asb + r * 528 + ch * 128 + c * 16,
                 A + (size_t)(m0 + r) * DD + ch * 64 + c * 8);
        }
        #pragma unroll
        for (int i = 0; i < 2; i++) {        // W: 64 rows x 8 segs
            int t = tid + i * 256;
            int r = t >> 3, c = t & 7;
            CP16(wsb + r * 528 + ch * 128 + c * 16,
                 Wt + (size_t)(n0 + r) * DD + ch * 64 + c * 8);
        }
        CP_COMMIT();
    }

    int grp = lane >> 3, lrow = lane & 7;
    int rowA  = ((grp & 1) << 3) + lrow;
    int koffA = (grp >> 1) << 4;
    int rowB  = ((grp >> 1) << 3) + lrow;
    int koffB = (grp & 1) << 4;

    float acc[2][4][4];
    #pragma unroll
    for (int mt = 0; mt < 2; mt++)
        #pragma unroll
        for (int nt = 0; nt < 4; nt++)
            #pragma unroll
            for (int v = 0; v < 4; v++) acc[mt][nt][v] = 0.0f;

    #pragma unroll
    for (int ch = 0; ch < 4; ch++) {
        switch (ch) {   // compile-time immediates after unroll
            case 0: CP_WAIT(3); break;
            case 1: CP_WAIT(2); break;
            case 2: CP_WAIT(1); break;
            default: CP_WAIT(0); break;
        }
        __syncthreads();
        #pragma unroll
        for (int k2 = 0; k2 < 4; k2++) {
            int kk = ch * 4 + k2;
            uint32_t af[2][4], b0[4], b1[4];
            ldsm4(af[0], asb + (wm + rowA) * 528 + kk * 32 + koffA);
            ldsm4(af[1], asb + (wm + 16 + rowA) * 528 + kk * 32 + koffA);
            ldsm4(b0, wsb + (wn + rowB) * 528 + kk * 32 + koffB);
            ldsm4(b1, wsb + (wn + 16 + rowB) * 528 + kk * 32 + koffB);
            #pragma unroll
            for (int mt = 0; mt < 2; mt++) {
                mma_bf16(acc[mt][0], af[mt], &b0[0]);
                mma_bf16(acc[mt][1], af[mt], &b0[2]);
                mma_bf16(acc[mt][2], af[mt], &b1[0]);
                mma_bf16(acc[mt][3], af[mt], &b1[2]);
            }
        }
    }

    int g = lane >> 2, t2 = (lane & 3) * 2;
    #pragma unroll
    for (int mt = 0; mt < 2; mt++) {
        #pragma unroll
        for (int half = 0; half < 2; half++) {
            int m = m0 + wm + mt * 16 + g + half * 8;
            if (Cf) {
                float mk = mask[m];
                #pragma unroll
                for (int nt = 0; nt < 4; nt++) {
                    int n = n0 + wn + nt * 8 + t2;
                    float2 bb = *(const float2*)(bias + n);
                    float2 rv = *(const float2*)(resid + (size_t)m * DD + n);
                    float cx = (acc[mt][nt][half * 2 + 0] + bb.x + rv.x) * mk;
                    float cy = (acc[mt][nt][half * 2 + 1] + bb.y + rv.y) * mk;
                    *(float2*)(Cf + (size_t)m * DD + n) = make_float2(cx, cy);
                }
            } else {
                #pragma unroll
                for (int nt = 0; nt < 4; nt++) {
                    int n = n0 + wn + nt * 8 + t2;
                    float2 bb = *(const float2*)(bias + n);
                    uint32_t p = packbf(acc[mt][nt][half * 2 + 0] + bb.x,
                                        acc[mt][nt][half * 2 + 1] + bb.y);
                    *(uint32_t*)(Cb + (size_t)m * ldc + n) = p;
                }
            }
        }
    }
}

// ---------------- per-edge score+softmax+PV, tensor cores ----------------
template <int NKB>
__device__ __forceinline__ void attn_edge(uint32_t ksb, uint32_t vsb,
                                          const uint32_t (&qf)[4][4],
                                          float (&acc)[8][4],
                                          int k_len, int lane) {
    int grp = lane >> 3, lrow = lane & 7;
    int rowB  = ((grp >> 1) << 3) + lrow;
    int koffB = (grp & 1) << 4;

    float sc[2 * NKB][4];
    #pragma unroll
    for (int nt = 0; nt < 2 * NKB; nt++)
        #pragma unroll
        for (int v = 0; v < 4; v++) sc[nt][v] = 0.0f;

    #pragma unroll
    for (int ds = 0; ds < 4; ds++) {
        #pragma unroll
        for (int g2 = 0; g2 < NKB; g2++) {
            uint32_t bf[4];
            ldsm4(bf, ksb + (g2 * 16 + rowB) * 144 + ds * 32 + koffB);
            mma_bf16(sc[2 * g2],     qf[ds], &bf[0]);
            mma_bf16(sc[2 * g2 + 1], qf[ds], &bf[2]);
        }
    }

    int cb = 2 * (lane & 3);
    float m1 = -1e30f, m2 = -1e30f;
    #pragma unroll
    for (int nt = 0; nt < 2 * NKB; nt++) {
        int c0 = nt * 8 + cb;
        bool v0 = c0 < k_len, v1 = (c0 + 1) < k_len;
        sc[nt][0] = v0 ? sc[nt][0] * 0.125f : -1e30f;
        sc[nt][1] = v1 ? sc[nt][1] * 0.125f : -1e30f;
        sc[nt][2] = v0 ? sc[nt][2] * 0.125f : -1e30f;
        sc[nt][3] = v1 ? sc[nt][3] * 0.125f : -1e30f;
        m1 = fmaxf(m1, fmaxf(sc[nt][0], sc[nt][1]));
        m2 = fmaxf(m2, fmaxf(sc[nt][2], sc[nt][3]));
    }
    m1 = fmaxf(m1, __shfl_xor_sync(0xffffffffu, m1, 1));
    m1 = fmaxf(m1, __shfl_xor_sync(0xffffffffu, m1, 2));
    m2 = fmaxf(m2, __shfl_xor_sync(0xffffffffu, m2, 1));
    m2 = fmaxf(m2, __shfl_xor_sync(0xffffffffu, m2, 2));

    float s1 = 0.0f, s2 = 0.0f;
    #pragma unroll
    for (int nt = 0; nt < 2 * NKB; nt++) {
        if (nt * 8 < k_len) {
            sc[nt][0] = __expf(sc[nt][0] - m1);
            sc[nt][1] = __expf(sc[nt][1] - m1);
            sc[nt][2] = __expf(sc[nt][2] - m2);
            sc[nt][3] = __expf(sc[nt][3] - m2);
        } else {
            sc[nt][0] = sc[nt][1] = sc[nt][2] = sc[nt][3] = 0.0f;
        }
        s1 += sc[nt][0] + sc[nt][1];
        s2 += sc[nt][2] + sc[nt][3];
    }
    s1 += __shfl_xor_sync(0xffffffffu, s1, 1);
    s1 += __shfl_xor_sync(0xffffffffu, s1, 2);
    s2 += __shfl_xor_sync(0xffffffffu, s2, 1);
    s2 += __shfl_xor_sync(0xffffffffu, s2, 2);
    float i1 = 1.0f / s1, i2 = 1.0f / s2;

    #pragma unroll
    for (int kb = 0; kb < NKB; kb++) {
        uint32_t pr[4];
        pr[0] = packbf(sc[2 * kb][0] * i1,     sc[2 * kb][1] * i1);
        pr[1] = packbf(sc[2 * kb][2] * i2,     sc[2 * kb][3] * i2);
        pr[2] = packbf(sc[2 * kb + 1][0] * i1, sc[2 * kb + 1][1] * i1);
        pr[3] = packbf(sc[2 * kb + 1][2] * i2, sc[2 * kb + 1][3] * i2);
        #pragma unroll
        for (int dg = 0; dg < 4; dg++) {
            uint32_t vb[4];
            ldsm4t(vb, vsb + (kb * 16 + ((grp & 1) << 3) + lrow) * 144
                          + dg * 32 + ((grp >> 1) << 4));
            mma_bf16(acc[dg * 2],     pr, &vb[0]);
            mma_bf16(acc[dg * 2 + 1], pr, &vb[2]);
        }
    }
}

// ---------------- per-(src,head) attention, cp.async double-buffered --------
#define KBUF (64 * 144)   // bytes per K/V buffer

__global__ __launch_bounds__(128) void attn2(const __nv_bfloat16* __restrict__ qkv) {
    __shared__ __align__(16) __nv_bfloat16 Qs[64 * 72];
    __shared__ __align__(16) __nv_bfloat16 Ks[2 * 64 * 72];
    __shared__ __align__(16) __nv_bfloat16 Vs[2 * 64 * 72];

    int src = blockIdx.x >> 2;
    int h   = blockIdx.x & 3;
    int tid = threadIdx.x;
    int w = tid >> 5, lane = tid & 31;

    #pragma unroll
    for (int i = 0; i < 4; i++) {
        int t = tid + i * 128;
        int r = t >> 3, c = t & 7;
        *(uint4*)&Qs[r * 72 + c * 8] =
            *(const uint4*)(qkv + (size_t)(src * SS + r) * 768 + h * HDIM + c * 8);
    }
    __syncthreads();

    uint32_t qsb = (uint32_t)__cvta_generic_to_shared(Qs);
    uint32_t ksb = (uint32_t)__cvta_generic_to_shared(Ks);
    uint32_t vsb = (uint32_t)__cvta_generic_to_shared(Vs);

    int grp = lane >> 3, lrow = lane & 7;
    int rowA  = ((grp & 1) << 3) + lrow;
    int koffA = (grp >> 1) << 4;

    uint32_t qf[4][4];
    #pragma unroll
    for (int ds = 0; ds < 4; ds++)
        ldsm4(qf[ds], qsb + (16 * w + rowA) * 144 + ds * 32 + koffA);

    float acc[8][4];
    #pragma unroll
    for (int i = 0; i < 8; i++)
        #pragma unroll
        for (int v = 0; v < 4; v++) acc[i][v] = 0.0f;

    int q_len = g_len[src];
    bool act = (16 * w < q_len);
    int e0 = g_off[src], e1 = g_off[src + 1];

    if (e0 < e1) {   // prologue: stage first edge into buffer 0
        int dst = g_adj[e0];
        int rup = ((g_len[dst] + 15) >> 4) << 4;
        for (int t = tid; t < rup * 8; t += 128) {
            int r = t >> 3, c = t & 7;
            size_t base = (size_t)(dst * SS + r) * 768 + h * HDIM + c * 8;
            CP16(ksb + r * 144 + c * 16, qkv + base + 256);
            CP16(vsb + r * 144 + c * 16, qkv + base + 512);
        }
        CP_COMMIT();
    }

    for (int e = e0; e < e1; e++) {
        int buf = (e - e0) & 1;
        int k_len = g_len[g_adj[e]];
        int nkb = (k_len + 15) >> 4;
        bool more = (e + 1 < e1);

        if (more) {   // prefetch next edge into the other buffer
            int d2 = g_adj[e + 1];
            int rup2 = ((g_len[d2] + 15) >> 4) << 4;
            int ob = buf ^ 1;
            for (int t = tid; t < rup2 * 8; t += 128) {
                int r = t >> 3, c = t & 7;
                size_t base = (size_t)(d2 * SS + r) * 768 + h * HDIM + c * 8;
                CP16(ksb + ob * KBUF + r * 144 + c * 16, qkv + base + 256);
                CP16(vsb + ob * KBUF + r * 144 + c * 16, qkv + base + 512);
            }
            CP_COMMIT();
            CP_WAIT(1);   // current edge's group done; next may be in flight
        } else {
            CP_WAIT(0);
        }
        __syncthreads();

        if (act) {
            switch (nkb) {
                case 1:  attn_edge<1>(ksb + buf * KBUF, vsb + buf * KBUF, qf, acc, k_len, lane); break;
                case 2:  attn_edge<2>(ksb + buf * KBUF, vsb + buf * KBUF, qf, acc, k_len, lane); break;
                case 3:  attn_edge<3>(ksb + buf * KBUF, vsb + buf * KBUF, qf, acc, k_len, lane); break;
                default: attn_edge<4>(ksb + buf * KBUF, vsb + buf * KBUF, qf, acc, k_len, lane); break;
            }
        }
        __syncthreads();   // buffer `buf` free before it is re-staged at e+2
    }

    int r1 = 16 * w + (lane >> 2);
    int t2 = 2 * (lane & 3);
    #pragma unroll
    for (int dt = 0; dt < 8; dt++) {
        size_t b1 = (size_t)(src * SS + r1) * DD + h * HDIM + dt * 8 + t2;
        size_t b2 = (size_t)(src * SS + r1 + 8) * DD + h * HDIM + dt * 8 + t2;
        *(uint32_t*)(g_ctxb + b1) = packbf(acc[dt][0], acc[dt][1]);
        *(uint32_t*)(g_ctxb + b2) = packbf(acc[dt][2], acc[dt][3]);
    }
}

// ---------------- launcher ----------------
extern "C" void kernel_launch(void* const* d_in, const int* in_sizes, int n_in,
                              void* d_out, int out_size) {
    const float* nf = (const float*)d_in[0];
    const float* nm = (const float*)d_in[1];
    const float* lw = (const float*)d_in[2];
    const float* lb = (const float*)d_in[3];
    const float* wq = (const float*)d_in[4];
    const float* bq = (const float*)d_in[5];
    const float* wk = (const float*)d_in[6];
    const float* bk = (const float*)d_in[7];
    const float* wv = (const float*)d_in[8];
    const float* bv = (const float*)d_in[9];
    const float* wo = (const float*)d_in[10];
    const float* bo = (const float*)d_in[11];
    const int* ei32 = (const int*)d_in[13];
    float* out = (float*)d_out;

    __nv_bfloat16 *p_xnb, *p_qkvb, *p_ctxb, *p_wtb;
    float* p_bqkv;
    cudaGetSymbolAddress((void**)&p_xnb,  g_xnb);
    cudaGetSymbolAddress((void**)&p_qkvb, g_qkvb);
    cudaGetSymbolAddress((void**)&p_ctxb, g_ctxb);
    cudaGetSymbolAddress((void**)&p_wtb,  g_wtb);
    cudaGetSymbolAddress((void**)&p_bqkv, g_bqkv);

    static const int GEMM_SMEM = (128 + 64) * 264 * 2;  // 101376 B
    cudaFuncSetAttribute(gemm2, cudaFuncAttributeMaxDynamicSharedMemorySize, GEMM_SMEM);

    graph_kernel<<<1, 1024>>>(ei32, nm);                             // 1
    csr_scatter<<<EE / 256, 256>>>(ei32);                            // 2
    wtb_kernel<<<1027, 256>>>(wq, wk, wv, wo, bq, bk, bv);           // 3
    ln_kernel<<<MROWS / 8, 256>>>(nf, lw, lb);                       // 4

    dim3 gqkv(12, 512);                                              // 5: fused QKV
    gemm2<<<gqkv, 256, GEMM_SMEM>>>(p_xnb, p_wtb, p_bqkv,
                                    p_qkvb, 768, nullptr, nullptr, nullptr);

    attn2<<<NN * HH, 128>>>(p_qkvb);                                 // 6 (profiled)

    dim3 go(4, 512);                                                 // 7: out-proj
    gemm2<<<go, 256, GEMM_SMEM>>>(p_ctxb, p_wtb + 768 * DD, bo,
                                  nullptr, 0, out, nf, nm);
}

// round 8
// speedup vs baseline: 1.0074x; 1.0074x over previous
#include <cuda_runtime.h>
#include <cuda_bf16.h>
#include <cstdint>

// Problem constants (fixed by the reference)
#define NN 1024
#define SS 64
#define DD 256
#define HH 4
#define HDIM 64
#define EE 4096
#define MROWS (NN * SS)   // 65536

// ---------------- scratch (device globals; no allocs allowed) ----------------
__device__ __nv_bfloat16 g_xnb[MROWS * DD];     // layernormed features (bf16)
__device__ __nv_bfloat16 g_qkvb[MROWS * 768];   // stacked q|k|v (bf16)
__device__ __nv_bfloat16 g_ctxb[MROWS * DD];    // per-src summed context (bf16)
__device__ __nv_bfloat16 g_wtb[4 * DD * DD];    // stacked weights [n][k]: wq,wk,wv,wo
__device__ float g_bqkv[768];                   // stacked biases bq|bk|bv
__device__ int g_off[NN + 1];
__device__ int g_adj[EE];
__device__ int g_len[NN];
__device__ int g_step;

// ---------------- mma helpers ----------------
__device__ __forceinline__ void ldsm4(uint32_t* r, uint32_t addr) {
    asm volatile("ldmatrix.sync.aligned.m8n8.x4.shared.b16 {%0,%1,%2,%3}, [%4];\n"
                 : "=r"(r[0]), "=r"(r[1]), "=r"(r[2]), "=r"(r[3]) : "r"(addr));
}

__device__ __forceinline__ void ldsm4t(uint32_t* r, uint32_t addr) {
    asm volatile("ldmatrix.sync.aligned.m8n8.x4.trans.shared.b16 {%0,%1,%2,%3}, [%4];\n"
                 : "=r"(r[0]), "=r"(r[1]), "=r"(r[2]), "=r"(r[3]) : "r"(addr));
}

__device__ __forceinline__ void mma_bf16(float* d, const uint32_t* a, const uint32_t* b) {
    asm volatile(
        "mma.sync.aligned.m16n8k16.row.col.f32.bf16.bf16.f32 "
        "{%0,%1,%2,%3}, {%4,%5,%6,%7}, {%8,%9}, {%0,%1,%2,%3};\n"
        : "+f"(d[0]), "+f"(d[1]), "+f"(d[2]), "+f"(d[3])
        : "r"(a[0]), "r"(a[1]), "r"(a[2]), "r"(a[3]), "r"(b[0]), "r"(b[1]));
}

__device__ __forceinline__ uint32_t packbf(float x, float y) {
    __nv_bfloat162 p = __floats2bfloat162_rn(x, y);
    return *(uint32_t*)&p;
}

#define CP16(dst, src) \
    asm volatile("cp.async.cg.shared.global [%0], [%1], 16;\n" :: "r"(dst), "l"(src))
#define CP_COMMIT() asm volatile("cp.async.commit_group;\n" ::: "memory")
#define CP_WAIT(n)  asm volatile("cp.async.wait_group %0;\n" :: "n"(n) : "memory")

// ---------------- fused graph preprocessing: detect + len + hist + scan -----
__global__ __launch_bounds__(1024) void graph_kernel(const int* __restrict__ ei32,
                                                     const float* __restrict__ masks) {
    __shared__ int s[NN];
    int t = threadIdx.x;

    // dtype detection: int64 edge ids have zero high words
    int nz = 0;
    for (int i = t; i < EE; i += 1024) nz |= (ei32[2 * i + 1] != 0);
    nz = __syncthreads_or(nz);
    int step = nz ? 1 : 2;
    if (t == 0) g_step = step;

    // lengths (prefix masks)
    {
        int c = 0;
        #pragma unroll 8
        for (int q = 0; q < SS; q++) c += (masks[t * SS + q] > 0.0f);
        g_len[t] = c;
    }

    // histogram of src
    s[t] = 0;
    __syncthreads();
    for (int e = t; e < EE; e += 1024) atomicAdd(&s[ei32[step * e]], 1);
    __syncthreads();

    // inclusive scan (Hillis-Steele)
    for (int o = 1; o < NN; o <<= 1) {
        int v = (t >= o) ? s[t - o] : 0;
        __syncthreads();
        s[t] += v;
        __syncthreads();
    }
    g_off[t + 1] = s[t];
    if (t == 0) g_off[0] = 0;
}

__global__ void csr_scatter(const int* __restrict__ ei32) {
    int e = blockIdx.x * blockDim.x + threadIdx.x;
    if (e >= EE) return;
    int step = g_step;
    int src = ei32[step * e];
    int cnt = 0;  // rank among earlier edges with same src -> deterministic
    for (int j = 0; j < e; j++) cnt += (ei32[step * j] == src);
    g_adj[g_off[src] + cnt] = ei32[step * (EE + e)];
}

// ---------------- weights (stacked transpose + bf16) + biases ----------------
__global__ void wtb_kernel(const float* __restrict__ wq, const float* __restrict__ wk,
                           const float* __restrict__ wv, const float* __restrict__ wo,
                           const float* __restrict__ bq, const float* __restrict__ bk,
                           const float* __restrict__ bv) {
    int bx = blockIdx.x;
    if (bx >= 1024) {   // bias blocks
        int i = (bx - 1024) * 256 + threadIdx.x;  // 0..767
        g_bqkv[i] = (i < 256) ? bq[i] : (i < 512) ? bk[i - 256] : bv[i - 512];
        return;
    }
    const float* w = (bx < 256) ? wq : (bx < 512) ? wk : (bx < 768) ? wv : wo;
    int n = bx & 255;
    for (int k = threadIdx.x; k < DD; k += blockDim.x)
        g_wtb[bx * DD + k] = __float2bfloat16(w[k * DD + n]);
}

// ---------------- LayerNorm -> bf16 output ----------------
__global__ __launch_bounds__(256) void ln_kernel(const float* __restrict__ x,
                                                 const float* __restrict__ w,
                                                 const float* __restrict__ b) {
    int warp = (blockIdx.x * blockDim.x + threadIdx.x) >> 5;
    int lane = threadIdx.x & 31;
    if (warp >= MROWS) return;
    const float* xr = x + (size_t)warp * DD + lane * 8;
    float4 a = *(const float4*)xr;
    float4 c = *(const float4*)(xr + 4);
    float s  = a.x + a.y + a.z + a.w + c.x + c.y + c.z + c.w;
    float s2 = a.x*a.x + a.y*a.y + a.z*a.z + a.w*a.w
             + c.x*c.x + c.y*c.y + c.z*c.z + c.w*c.w;
    #pragma unroll
    for (int o = 16; o > 0; o >>= 1) {
        s  += __shfl_xor_sync(0xffffffffu, s,  o);
        s2 += __shfl_xor_sync(0xffffffffu, s2, o);
    }
    float mu  = s * (1.0f / DD);
    float var = s2 * (1.0f / DD) - mu * mu;
    float r = rsqrtf(var + 1e-5f);
    float4 w0 = *(const float4*)(w + lane * 8);
    float4 w1 = *(const float4*)(w + lane * 8 + 4);
    float4 b0 = *(const float4*)(b + lane * 8);
    float4 b1 = *(const float4*)(b + lane * 8 + 4);
    float o0x = (a.x - mu) * r * w0.x + b0.x, o0y = (a.y - mu) * r * w0.y + b0.y;
    float o0z = (a.z - mu) * r * w0.z + b0.z, o0w = (a.w - mu) * r * w0.w + b0.w;
    float o1x = (c.x - mu) * r * w1.x + b1.x, o1y = (c.y - mu) * r * w1.y + b1.y;
    float o1z = (c.z - mu) * r * w1.z + b1.z, o1w = (c.w - mu) * r * w1.w + b1.w;
    uint4 u = make_uint4(packbf(o0x, o0y), packbf(o0z, o0w),
                         packbf(o1x, o1y), packbf(o1z, o1w));
    *(uint4*)(g_xnb + (size_t)warp * DD + lane * 8) = u;
}

// ---------------- full-K bf16 GEMM, chunk-pipelined staging ------------------
// CTA tile 128m x 64n, K=256 staged as 4 cp.async commit groups of K=64;
// compute starts after chunk 0 lands (wait_group 3..0). 8 warps 4Mx2N.
__global__ __launch_bounds__(256) void gemm2(const __nv_bfloat16* __restrict__ A,
                                             const __nv_bfloat16* __restrict__ Wt,
                                             const float* __restrict__ bias,
                                             __nv_bfloat16* __restrict__ Cb, int ldc,
                                             float* __restrict__ Cf,
                                             const float* __restrict__ resid,
                                             const float* __restrict__ mask) {
    extern __shared__ __align__(16) __nv_bfloat16 smem2[];
    __nv_bfloat16* As = smem2;              // [128][264] (stride 528 B)
    __nv_bfloat16* Ws = smem2 + 128 * 264;  // [64][264]

    int tid = threadIdx.x;
    int wid = tid >> 5, lane = tid & 31;
    int m0 = blockIdx.y * 128, n0 = blockIdx.x * 64;
    int wm = (wid & 3) * 32, wn = (wid >> 2) * 32;

    uint32_t asb = (uint32_t)__cvta_generic_to_shared(As);
    uint32_t wsb = (uint32_t)__cvta_generic_to_shared(Ws);

    // stage K in 4 chunks of 64 (128 B per row-chunk), one commit group each
    #pragma unroll
    for (int ch = 0; ch < 4; ch++) {
        #pragma unroll
        for (int i = 0; i < 4; i++) {        // A: 128 rows x 8 segs
            int t = tid + i * 256;
            int r = t >> 3, c = t & 7;
            CP16(asb + r * 528 + ch * 128 + c * 16,
                 A + (size_t)(m0 + r) * DD + ch * 64 + c * 8);
        }
        #pragma unroll
        for (int i = 0; i < 2; i++) {        // W: 64 rows x 8 segs
            int t = tid + i * 256;
            int r = t >> 3, c = t & 7;
            CP16(wsb + r * 528 + ch * 128 + c * 16,
                 Wt + (size_t)(n0 + r) * DD + ch * 64 + c * 8);
        }
        CP_COMMIT();
    }

    int grp = lane >> 3, lrow = lane & 7;
    int rowA  = ((grp & 1) << 3) + lrow;
    int koffA = (grp >> 1) << 4;
    int rowB  = ((grp >> 1) << 3) + lrow;
    int koffB = (grp & 1) << 4;

    float acc[2][4][4];
    #pragma unroll
    for (int mt = 0; mt < 2; mt++)
        #pragma unroll
        for (int nt = 0; nt < 4; nt++)
            #pragma unroll
            for (int v = 0; v < 4; v++) acc[mt][nt][v] = 0.0f;

    #pragma unroll
    for (int ch = 0; ch < 4; ch++) {
        switch (ch) {   // compile-time immediates after unroll
            case 0: CP_WAIT(3); break;
            case 1: CP_WAIT(2); break;
            case 2: CP_WAIT(1); break;
            default: CP_WAIT(0); break;
        }
        __syncthreads();
        #pragma unroll
        for (int k2 = 0; k2 < 4; k2++) {
            int kk = ch * 4 + k2;
            uint32_t af[2][4], b0[4], b1[4];
            ldsm4(af[0], asb + (wm + rowA) * 528 + kk * 32 + koffA);
            ldsm4(af[1], asb + (wm + 16 + rowA) * 528 + kk * 32 + koffA);
            ldsm4(b0, wsb + (wn + rowB) * 528 + kk * 32 + koffB);
            ldsm4(b1, wsb + (wn + 16 + rowB) * 528 + kk * 32 + koffB);
            #pragma unroll
            for (int mt = 0; mt < 2; mt++) {
                mma_bf16(acc[mt][0], af[mt], &b0[0]);
                mma_bf16(acc[mt][1], af[mt], &b0[2]);
                mma_bf16(acc[mt][2], af[mt], &b1[0]);
                mma_bf16(acc[mt][3], af[mt], &b1[2]);
            }
        }
    }

    int g = lane >> 2, t2 = (lane & 3) * 2;
    #pragma unroll
    for (int mt = 0; mt < 2; mt++) {
        #pragma unroll
        for (int half = 0; half < 2; half++) {
            int m = m0 + wm + mt * 16 + g + half * 8;
            if (Cf) {
                float mk = mask[m];
                #pragma unroll
                for (int nt = 0; nt < 4; nt++) {
                    int n = n0 + wn + nt * 8 + t2;
                    float2 bb = *(const float2*)(bias + n);
                    float2 rv = *(const float2*)(resid + (size_t)m * DD + n);
                    float cx = (acc[mt][nt][half * 2 + 0] + bb.x + rv.x) * mk;
                    float cy = (acc[mt][nt][half * 2 + 1] + bb.y + rv.y) * mk;
                    *(float2*)(Cf + (size_t)m * DD + n) = make_float2(cx, cy);
                }
            } else {
                #pragma unroll
                for (int nt = 0; nt < 4; nt++) {
                    int n = n0 + wn + nt * 8 + t2;
                    float2 bb = *(const float2*)(bias + n);
                    uint32_t p = packbf(acc[mt][nt][half * 2 + 0] + bb.x,
                                        acc[mt][nt][half * 2 + 1] + bb.y);
                    *(uint32_t*)(Cb + (size_t)m * ldc + n) = p;
                }
            }
        }
    }
}

// ---------------- per-edge score+softmax+PV, tensor cores ----------------
template <int NKB>
__device__ __forceinline__ void attn_edge(uint32_t ksb, uint32_t vsb,
                                          const uint32_t (&qf)[4][4],
                                          float (&acc)[8][4],
                                          int k_len, int lane) {
    int grp = lane >> 3, lrow = lane & 7;
    int rowB  = ((grp >> 1) << 3) + lrow;
    int koffB = (grp & 1) << 4;

    float sc[2 * NKB][4];
    #pragma unroll
    for (int nt = 0; nt < 2 * NKB; nt++)
        #pragma unroll
        for (int v = 0; v < 4; v++) sc[nt][v] = 0.0f;

    #pragma unroll
    for (int ds = 0; ds < 4; ds++) {
        #pragma unroll
        for (int g2 = 0; g2 < NKB; g2++) {
            uint32_t bf[4];
            ldsm4(bf, ksb + (g2 * 16 + rowB) * 144 + ds * 32 + koffB);
            mma_bf16(sc[2 * g2],     qf[ds], &bf[0]);
            mma_bf16(sc[2 * g2 + 1], qf[ds], &bf[2]);
        }
    }

    int cb = 2 * (lane & 3);
    float m1 = -1e30f, m2 = -1e30f;
    #pragma unroll
    for (int nt = 0; nt < 2 * NKB; nt++) {
        int c0 = nt * 8 + cb;
        bool v0 = c0 < k_len, v1 = (c0 + 1) < k_len;
        sc[nt][0] = v0 ? sc[nt][0] * 0.125f : -1e30f;
        sc[nt][1] = v1 ? sc[nt][1] * 0.125f : -1e30f;
        sc[nt][2] = v0 ? sc[nt][2] * 0.125f : -1e30f;
        sc[nt][3] = v1 ? sc[nt][3] * 0.125f : -1e30f;
        m1 = fmaxf(m1, fmaxf(sc[nt][0], sc[nt][1]));
        m2 = fmaxf(m2, fmaxf(sc[nt][2], sc[nt][3]));
    }
    m1 = fmaxf(m1, __shfl_xor_sync(0xffffffffu, m1, 1));
    m1 = fmaxf(m1, __shfl_xor_sync(0xffffffffu, m1, 2));
    m2 = fmaxf(m2, __shfl_xor_sync(0xffffffffu, m2, 1));
    m2 = fmaxf(m2, __shfl_xor_sync(0xffffffffu, m2, 2));

    float s1 = 0.0f, s2 = 0.0f;
    #pragma unroll
    for (int nt = 0; nt < 2 * NKB; nt++) {
        if (nt * 8 < k_len) {
            sc[nt][0] = __expf(sc[nt][0] - m1);
            sc[nt][1] = __expf(sc[nt][1] - m1);
            sc[nt][2] = __expf(sc[nt][2] - m2);
            sc[nt][3] = __expf(sc[nt][3] - m2);
        } else {
            sc[nt][0] = sc[nt][1] = sc[nt][2] = sc[nt][3] = 0.0f;
        }
        s1 += sc[nt][0] + sc[nt][1];
        s2 += sc[nt][2] + sc[nt][3];
    }
    s1 += __shfl_xor_sync(0xffffffffu, s1, 1);
    s1 += __shfl_xor_sync(0xffffffffu, s1, 2);
    s2 += __shfl_xor_sync(0xffffffffu, s2, 1);
    s2 += __shfl_xor_sync(0xffffffffu, s2, 2);
    float i1 = 1.0f / s1, i2 = 1.0f / s2;

    #pragma unroll
    for (int kb = 0; kb < NKB; kb++) {
        uint32_t pr[4];
        pr[0] = packbf(sc[2 * kb][0] * i1,     sc[2 * kb][1] * i1);
        pr[1] = packbf(sc[2 * kb][2] * i2,     sc[2 * kb][3] * i2);
        pr[2] = packbf(sc[2 * kb + 1][0] * i1, sc[2 * kb + 1][1] * i1);
        pr[3] = packbf(sc[2 * kb + 1][2] * i2, sc[2 * kb + 1][3] * i2);
        #pragma unroll
        for (int dg = 0; dg < 4; dg++) {
            uint32_t vb[4];
            ldsm4t(vb, vsb + (kb * 16 + ((grp & 1) << 3) + lrow) * 144
                          + dg * 32 + ((grp >> 1) << 4));
            mma_bf16(acc[dg * 2],     pr, &vb[0]);
            mma_bf16(acc[dg * 2 + 1], pr, &vb[2]);
        }
    }
}

// ---------------- per-(src,head) attention (R6: single-buffer, high occ) ----
__global__ __launch_bounds__(128) void attn2(const __nv_bfloat16* __restrict__ qkv) {
    __shared__ __align__(16) __nv_bfloat16 Qs[64 * 72];
    __shared__ __align__(16) __nv_bfloat16 Ks[64 * 72];
    __shared__ __align__(16) __nv_bfloat16 Vs[64 * 72];

    int src = blockIdx.x >> 2;
    int h   = blockIdx.x & 3;
    int tid = threadIdx.x;
    int w = tid >> 5, lane = tid & 31;

    #pragma unroll
    for (int i = 0; i < 4; i++) {
        int t = tid + i * 128;
        int r = t >> 3, c = t & 7;
        *(uint4*)&Qs[r * 72 + c * 8] =
            *(const uint4*)(qkv + (size_t)(src * SS + r) * 768 + h * HDIM + c * 8);
    }
    __syncthreads();

    uint32_t qsb = (uint32_t)__cvta_generic_to_shared(Qs);
    uint32_t ksb = (uint32_t)__cvta_generic_to_shared(Ks);
    uint32_t vsb = (uint32_t)__cvta_generic_to_shared(Vs);

    int grp = lane >> 3, lrow = lane & 7;
    int rowA  = ((grp & 1) << 3) + lrow;
    int koffA = (grp >> 1) << 4;

    uint32_t qf[4][4];
    #pragma unroll
    for (int ds = 0; ds < 4; ds++)
        ldsm4(qf[ds], qsb + (16 * w + rowA) * 144 + ds * 32 + koffA);

    float acc[8][4];
    #pragma unroll
    for (int i = 0; i < 8; i++)
        #pragma unroll
        for (int v = 0; v < 4; v++) acc[i][v] = 0.0f;

    int q_len = g_len[src];
    bool act = (16 * w < q_len);
    int e0 = g_off[src], e1 = g_off[src + 1];

    for (int e = e0; e < e1; e++) {
        int dst = g_adj[e];
        int k_len = g_len[dst];
        int nkb = (k_len + 15) >> 4;          // 1..4
        int rup = nkb << 4;

        for (int t = tid; t < rup * 8; t += 128) {
            int r = t >> 3, c = t & 7;
            size_t base = (size_t)(dst * SS + r) * 768 + h * HDIM + c * 8;
            *(uint4*)&Ks[r * 72 + c * 8] = *(const uint4*)(qkv + base + 256);
            *(uint4*)&Vs[r * 72 + c * 8] = *(const uint4*)(qkv + base + 512);
        }
        __syncthreads();

        if (act) {
            switch (nkb) {
                case 1:  attn_edge<1>(ksb, vsb, qf, acc, k_len, lane); break;
                case 2:  attn_edge<2>(ksb, vsb, qf, acc, k_len, lane); break;
                case 3:  attn_edge<3>(ksb, vsb, qf, acc, k_len, lane); break;
                default: attn_edge<4>(ksb, vsb, qf, acc, k_len, lane); break;
            }
        }
        __syncthreads();
    }

    int r1 = 16 * w + (lane >> 2);
    int t2 = 2 * (lane & 3);
    #pragma unroll
    for (int dt = 0; dt < 8; dt++) {
        size_t b1 = (size_t)(src * SS + r1) * DD + h * HDIM + dt * 8 + t2;
        size_t b2 = (size_t)(src * SS + r1 + 8) * DD + h * HDIM + dt * 8 + t2;
        *(uint32_t*)(g_ctxb + b1) = packbf(acc[dt][0], acc[dt][1]);
        *(uint32_t*)(g_ctxb + b2) = packbf(acc[dt][2], acc[dt][3]);
    }
}

// ---------------- launcher ----------------
extern "C" void kernel_launch(void* const* d_in, const int* in_sizes, int n_in,
                              void* d_out, int out_size) {
    const float* nf = (const float*)d_in[0];
    const float* nm = (const float*)d_in[1];
    const float* lw = (const float*)d_in[2];
    const float* lb = (const float*)d_in[3];
    const float* wq = (const float*)d_in[4];
    const float* bq = (const float*)d_in[5];
    const float* wk = (const float*)d_in[6];
    const float* bk = (const float*)d_in[7];
    const float* wv = (const float*)d_in[8];
    const float* bv = (const float*)d_in[9];
    const float* wo = (const float*)d_in[10];
    const float* bo = (const float*)d_in[11];
    const int* ei32 = (const int*)d_in[13];
    float* out = (float*)d_out;

    __nv_bfloat16 *p_xnb, *p_qkvb, *p_ctxb, *p_wtb;
    float* p_bqkv;
    cudaGetSymbolAddress((void**)&p_xnb,  g_xnb);
    cudaGetSymbolAddress((void**)&p_qkvb, g_qkvb);
    cudaGetSymbolAddress((void**)&p_ctxb, g_ctxb);
    cudaGetSymbolAddress((void**)&p_wtb,  g_wtb);
    cudaGetSymbolAddress((void**)&p_bqkv, g_bqkv);

    static const int GEMM_SMEM = (128 + 64) * 264 * 2;  // 101376 B
    cudaFuncSetAttribute(gemm2, cudaFuncAttributeMaxDynamicSharedMemorySize, GEMM_SMEM);

    graph_kernel<<<1, 1024>>>(ei32, nm);                             // 1
    csr_scatter<<<EE / 256, 256>>>(ei32);                            // 2
    wtb_kernel<<<1027, 256>>>(wq, wk, wv, wo, bq, bk, bv);           // 3
    ln_kernel<<<MROWS / 8, 256>>>(nf, lw, lb);                       // 4

    dim3 gqkv(12, 512);                                              // 5: fused QKV
    gemm2<<<gqkv, 256, GEMM_SMEM>>>(p_xnb, p_wtb, p_bqkv,
                                    p_qkvb, 768, nullptr, nullptr, nullptr);

    attn2<<<NN * HH, 128>>>(p_qkvb);                                 // 6

    dim3 go(4, 512);                                                 // 7: out-proj
    gemm2<<<go, 256, GEMM_SMEM>>>(p_ctxb, p_wtb + 768 * DD, bo,
                                  nullptr, 0, out, nf, nm);
}

// round 11
// speedup vs baseline: 1.0799x; 1.0720x over previous
#include <cuda_runtime.h>
#include <cuda_bf16.h>
#include <cstdint>

// Problem constants (fixed by the reference)
#define NN 1024
#define SS 64
#define DD 256
#define HH 4
#define HDIM 64
#define EE 4096
#define MROWS (NN * SS)   // 65536

// ---------------- scratch (device globals; no allocs allowed) ----------------
__device__ __nv_bfloat16 g_xnb[MROWS * DD];     // layernormed features (bf16)
__device__ __nv_bfloat16 g_qkvb[MROWS * 768];   // stacked q|k|v (bf16)
__device__ __nv_bfloat16 g_ctxb[MROWS * DD];    // per-src summed context (bf16)
__device__ __nv_bfloat16 g_wtb[4 * DD * DD];    // stacked weights [n][k]: wq,wk,wv,wo
__device__ float g_bqkv[768];                   // stacked biases bq|bk|bv
__device__ int g_off[NN + 1];
__device__ int g_adj[EE];
__device__ int g_len[NN];
__device__ int g_step;

// ---------------- mma helpers ----------------
__device__ __forceinline__ void ldsm4(uint32_t* r, uint32_t addr) {
    asm volatile("ldmatrix.sync.aligned.m8n8.x4.shared.b16 {%0,%1,%2,%3}, [%4];\n"
                 : "=r"(r[0]), "=r"(r[1]), "=r"(r[2]), "=r"(r[3]) : "r"(addr));
}

__device__ __forceinline__ void ldsm4t(uint32_t* r, uint32_t addr) {
    asm volatile("ldmatrix.sync.aligned.m8n8.x4.trans.shared.b16 {%0,%1,%2,%3}, [%4];\n"
                 : "=r"(r[0]), "=r"(r[1]), "=r"(r[2]), "=r"(r[3]) : "r"(addr));
}

__device__ __forceinline__ void mma_bf16(float* d, const uint32_t* a, const uint32_t* b) {
    asm volatile(
        "mma.sync.aligned.m16n8k16.row.col.f32.bf16.bf16.f32 "
        "{%0,%1,%2,%3}, {%4,%5,%6,%7}, {%8,%9}, {%0,%1,%2,%3};\n"
        : "+f"(d[0]), "+f"(d[1]), "+f"(d[2]), "+f"(d[3])
        : "r"(a[0]), "r"(a[1]), "r"(a[2]), "r"(a[3]), "r"(b[0]), "r"(b[1]));
}

__device__ __forceinline__ uint32_t packbf(float x, float y) {
    __nv_bfloat162 p = __floats2bfloat162_rn(x, y);
    return *(uint32_t*)&p;
}

#define CP16(dst, src) \
    asm volatile("cp.async.cg.shared.global [%0], [%1], 16;\n" :: "r"(dst), "l"(src))
#define CP_COMMIT() asm volatile("cp.async.commit_group;\n" ::: "memory")
#define CP_WAIT(n)  asm volatile("cp.async.wait_group %0;\n" :: "n"(n) : "memory")

// ---------------- prep mega-kernel: wtb | bias | len | layernorm ------------
// Block regions: [0,1024) weight transpose+bf16, [1024,1027) bias stack,
// [1027,1155) lengths (warp-ballot), [1155,9347) layernorm.
__global__ __launch_bounds__(256) void prep_kernel(const float* __restrict__ x,
                                                   const float* __restrict__ lw,
                                                   const float* __restrict__ lb,
                                                   const float* __restrict__ masks,
                                                   const float* __restrict__ wq,
                                                   const float* __restrict__ wk,
                                                   const float* __restrict__ wv,
                                                   const float* __restrict__ wo,
                                                   const float* __restrict__ bq,
                                                   const float* __restrict__ bk,
                                                   const float* __restrict__ bv) {
    int bx = blockIdx.x;
    int tid = threadIdx.x;

    if (bx < 1024) {                 // weights: wtb[n][k] = bf16(w[k][n])
        const float* w = (bx < 256) ? wq : (bx < 512) ? wk : (bx < 768) ? wv : wo;
        int n = bx & 255;
        for (int k = tid; k < DD; k += 256)
            g_wtb[bx * DD + k] = __float2bfloat16(w[k * DD + n]);
        return;
    }
    if (bx < 1027) {                 // stacked biases
        int i = (bx - 1024) * 256 + tid;
        g_bqkv[i] = (i < 256) ? bq[i] : (i < 512) ? bk[i - 256] : bv[i - 512];
        return;
    }
    if (bx < 1155) {                 // lengths: one warp per node, ballot count
        int w = ((bx - 1027) * 256 + tid) >> 5;
        int lane = tid & 31;
        int a = masks[w * SS + lane] > 0.0f;
        int b2 = masks[w * SS + 32 + lane] > 0.0f;
        int c = __popc(__ballot_sync(0xffffffffu, a)) +
                __popc(__ballot_sync(0xffffffffu, b2));
        if (lane == 0) g_len[w] = c;
        return;
    }
    {                                // layernorm -> bf16, one warp per row
        int warp = ((bx - 1155) * 256 + tid) >> 5;
        int lane = tid & 31;
        const float* xr = x + (size_t)warp * DD + lane * 8;
        float4 a = *(const float4*)xr;
        float4 c = *(const float4*)(xr + 4);
        float s  = a.x + a.y + a.z + a.w + c.x + c.y + c.z + c.w;
        float s2 = a.x*a.x + a.y*a.y + a.z*a.z + a.w*a.w
                 + c.x*c.x + c.y*c.y + c.z*c.z + c.w*c.w;
        #pragma unroll
        for (int o = 16; o > 0; o >>= 1) {
            s  += __shfl_xor_sync(0xffffffffu, s,  o);
            s2 += __shfl_xor_sync(0xffffffffu, s2, o);
        }
        float mu  = s * (1.0f / DD);
        float var = s2 * (1.0f / DD) - mu * mu;
        float r = rsqrtf(var + 1e-5f);
        float4 w0 = *(const float4*)(lw + lane * 8);
        float4 w1 = *(const float4*)(lw + lane * 8 + 4);
        float4 b0 = *(const float4*)(lb + lane * 8);
        float4 b1 = *(const float4*)(lb + lane * 8 + 4);
        float o0x = (a.x - mu) * r * w0.x + b0.x, o0y = (a.y - mu) * r * w0.y + b0.y;
        float o0z = (a.z - mu) * r * w0.z + b0.z, o0w = (a.w - mu) * r * w0.w + b0.w;
        float o1x = (c.x - mu) * r * w1.x + b1.x, o1y = (c.y - mu) * r * w1.y + b1.y;
        float o1z = (c.z - mu) * r * w1.z + b1.z, o1w = (c.w - mu) * r * w1.w + b1.w;
        uint4 u = make_uint4(packbf(o0x, o0y), packbf(o0z, o0w),
                             packbf(o1x, o1y), packbf(o1z, o1w));
        *(uint4*)(g_xnb + (size_t)warp * DD + lane * 8) = u;
    }
}

// ---------------- graph kernel: detect + histogram + scan (tiny, 1 block) ---
__global__ __launch_bounds__(1024) void graph_kernel(const int* __restrict__ ei32) {
    __shared__ int s[NN];
    int t = threadIdx.x;

    int nz = 0;
    for (int i = t; i < EE; i += 1024) nz |= (ei32[2 * i + 1] != 0);
    nz = __syncthreads_or(nz);
    int step = nz ? 1 : 2;
    if (t == 0) g_step = step;

    s[t] = 0;
    __syncthreads();
    for (int e = t; e < EE; e += 1024) atomicAdd(&s[ei32[step * e]], 1);
    __syncthreads();

    for (int o = 1; o < NN; o <<= 1) {
        int v = (t >= o) ? s[t - o] : 0;
        __syncthreads();
        s[t] += v;
        __syncthreads();
    }
    g_off[t + 1] = s[t];
    if (t == 0) g_off[0] = 0;
}

__global__ void csr_scatter(const int* __restrict__ ei32) {
    int e = blockIdx.x * blockDim.x + threadIdx.x;
    if (e >= EE) return;
    int step = g_step;
    int src = ei32[step * e];
    int cnt = 0;  // rank among earlier edges with same src -> deterministic
    for (int j = 0; j < e; j++) cnt += (ei32[step * j] == src);
    g_adj[g_off[src] + cnt] = ei32[step * (EE + e)];
}

// ---------------- full-K single-stage bf16 GEMM (R6-proven) ------------------
// CTA tile 128m x 64n, K=256 staged entirely (one cp.async batch, one sync).
// 8 warps: 4M x 2N, warp 32x32, mma m16n8k16, 16 straight-line k-steps.
__global__ __launch_bounds__(256) void gemm2(const __nv_bfloat16* __restrict__ A,
                                             const __nv_bfloat16* __restrict__ Wt,
                                             const float* __restrict__ bias,
                                             __nv_bfloat16* __restrict__ Cb, int ldc,
                                             float* __restrict__ Cf,
                                             const float* __restrict__ resid,
                                             const float* __restrict__ mask) {
    extern __shared__ __align__(16) __nv_bfloat16 smem2[];
    __nv_bfloat16* As = smem2;              // [128][264] (stride 528 B)
    __nv_bfloat16* Ws = smem2 + 128 * 264;  // [64][264]

    int tid = threadIdx.x;
    int wid = tid >> 5, lane = tid & 31;
    int m0 = blockIdx.y * 128, n0 = blockIdx.x * 64;
    int wm = (wid & 3) * 32, wn = (wid >> 2) * 32;

    uint32_t asb = (uint32_t)__cvta_generic_to_shared(As);
    uint32_t wsb = (uint32_t)__cvta_generic_to_shared(Ws);

    // stage the whole K range
    #pragma unroll
    for (int i = 0; i < 16; i++) {
        int t = tid + i * 256;               // 4096 chunks: 128 rows x 32
        int r = t >> 5, c = t & 31;
        CP16(asb + r * 528 + c * 16, A + (size_t)(m0 + r) * DD + c * 8);
    }
    #pragma unroll
    for (int i = 0; i < 8; i++) {
        int t = tid + i * 256;               // 2048 chunks: 64 rows x 32
        int r = t >> 5, c = t & 31;
        CP16(wsb + r * 528 + c * 16, Wt + (size_t)(n0 + r) * DD + c * 8);
    }
    CP_COMMIT();

    int grp = lane >> 3, lrow = lane & 7;
    int rowA  = ((grp & 1) << 3) + lrow;
    int koffA = (grp >> 1) << 4;
    int rowB  = ((grp >> 1) << 3) + lrow;
    int koffB = (grp & 1) << 4;

    float acc[2][4][4];
    #pragma unroll
    for (int mt = 0; mt < 2; mt++)
        #pragma unroll
        for (int nt = 0; nt < 4; nt++)
            #pragma unroll
            for (int v = 0; v < 4; v++) acc[mt][nt][v] = 0.0f;

    CP_WAIT(0);
    __syncthreads();

    #pragma unroll
    for (int kk = 0; kk < 16; kk++) {
        uint32_t af[2][4], b0[4], b1[4];
        ldsm4(af[0], asb + (wm + rowA) * 528 + kk * 32 + koffA);
        ldsm4(af[1], asb + (wm + 16 + rowA) * 528 + kk * 32 + koffA);
        ldsm4(b0, wsb + (wn + rowB) * 528 + kk * 32 + koffB);
        ldsm4(b1, wsb + (wn + 16 + rowB) * 528 + kk * 32 + koffB);
        #pragma unroll
        for (int mt = 0; mt < 2; mt++) {
            mma_bf16(acc[mt][0], af[mt], &b0[0]);
            mma_bf16(acc[mt][1], af[mt], &b0[2]);
            mma_bf16(acc[mt][2], af[mt], &b1[0]);
            mma_bf16(acc[mt][3], af[mt], &b1[2]);
        }
    }

    int g = lane >> 2, t2 = (lane & 3) * 2;
    #pragma unroll
    for (int mt = 0; mt < 2; mt++) {
        #pragma unroll
        for (int half = 0; half < 2; half++) {
            int m = m0 + wm + mt * 16 + g + half * 8;
            if (Cf) {
                float mk = mask[m];
                #pragma unroll
                for (int nt = 0; nt < 4; nt++) {
                    int n = n0 + wn + nt * 8 + t2;
                    float2 bb = *(const float2*)(bias + n);
                    float2 rv = *(const float2*)(resid + (size_t)m * DD + n);
                    float cx = (acc[mt][nt][half * 2 + 0] + bb.x + rv.x) * mk;
                    float cy = (acc[mt][nt][half * 2 + 1] + bb.y + rv.y) * mk;
                    *(float2*)(Cf + (size_t)m * DD + n) = make_float2(cx, cy);
                }
            } else {
                #pragma unroll
                for (int nt = 0; nt < 4; nt++) {
                    int n = n0 + wn + nt * 8 + t2;
                    float2 bb = *(const float2*)(bias + n);
                    uint32_t p = packbf(acc[mt][nt][half * 2 + 0] + bb.x,
                                        acc[mt][nt][half * 2 + 1] + bb.y);
                    *(uint32_t*)(Cb + (size_t)m * ldc + n) = p;
                }
            }
        }
    }
}

// ---------------- per-edge score+softmax+PV, tensor cores ----------------
template <int NKB>
__device__ __forceinline__ void attn_edge(uint32_t ksb, uint32_t vsb,
                                          const uint32_t (&qf)[4][4],
                                          float (&acc)[8][4],
                                          int k_len, int lane) {
    int grp = lane >> 3, lrow = lane & 7;
    int rowB  = ((grp >> 1) << 3) + lrow;
    int koffB = (grp & 1) << 4;

    float sc[2 * NKB][4];
    #pragma unroll
    for (int nt = 0; nt < 2 * NKB; nt++)
        #pragma unroll
        for (int v = 0; v < 4; v++) sc[nt][v] = 0.0f;

    #pragma unroll
    for (int ds = 0; ds < 4; ds++) {
        #pragma unroll
        for (int g2 = 0; g2 < NKB; g2++) {
            uint32_t bf[4];
            ldsm4(bf, ksb + (g2 * 16 + rowB) * 144 + ds * 32 + koffB);
            mma_bf16(sc[2 * g2],     qf[ds], &bf[0]);
            mma_bf16(sc[2 * g2 + 1], qf[ds], &bf[2]);
        }
    }

    int cb = 2 * (lane & 3);
    float m1 = -1e30f, m2 = -1e30f;
    #pragma unroll
    for (int nt = 0; nt < 2 * NKB; nt++) {
        int c0 = nt * 8 + cb;
        bool v0 = c0 < k_len, v1 = (c0 + 1) < k_len;
        sc[nt][0] = v0 ? sc[nt][0] * 0.125f : -1e30f;
        sc[nt][1] = v1 ? sc[nt][1] * 0.125f : -1e30f;
        sc[nt][2] = v0 ? sc[nt][2] * 0.125f : -1e30f;
        sc[nt][3] = v1 ? sc[nt][3] * 0.125f : -1e30f;
        m1 = fmaxf(m1, fmaxf(sc[nt][0], sc[nt][1]));
        m2 = fmaxf(m2, fmaxf(sc[nt][2], sc[nt][3]));
    }
    m1 = fmaxf(m1, __shfl_xor_sync(0xffffffffu, m1, 1));
    m1 = fmaxf(m1, __shfl_xor_sync(0xffffffffu, m1, 2));
    m2 = fmaxf(m2, __shfl_xor_sync(0xffffffffu, m2, 1));
    m2 = fmaxf(m2, __shfl_xor_sync(0xffffffffu, m2, 2));

    float s1 = 0.0f, s2 = 0.0f;
    #pragma unroll
    for (int nt = 0; nt < 2 * NKB; nt++) {
        if (nt * 8 < k_len) {
            sc[nt][0] = __expf(sc[nt][0] - m1);
            sc[nt][1] = __expf(sc[nt][1] - m1);
            sc[nt][2] = __expf(sc[nt][2] - m2);
            sc[nt][3] = __expf(sc[nt][3] - m2);
        } else {
            sc[nt][0] = sc[nt][1] = sc[nt][2] = sc[nt][3] = 0.0f;
        }
        s1 += sc[nt][0] + sc[nt][1];
        s2 += sc[nt][2] + sc[nt][3];
    }
    s1 += __shfl_xor_sync(0xffffffffu, s1, 1);
    s1 += __shfl_xor_sync(0xffffffffu, s1, 2);
    s2 += __shfl_xor_sync(0xffffffffu, s2, 1);
    s2 += __shfl_xor_sync(0xffffffffu, s2, 2);
    float i1 = 1.0f / s1, i2 = 1.0f / s2;

    #pragma unroll
    for (int kb = 0; kb < NKB; kb++) {
        uint32_t pr[4];
        pr[0] = packbf(sc[2 * kb][0] * i1,     sc[2 * kb][1] * i1);
        pr[1] = packbf(sc[2 * kb][2] * i2,     sc[2 * kb][3] * i2);
        pr[2] = packbf(sc[2 * kb + 1][0] * i1, sc[2 * kb + 1][1] * i1);
        pr[3] = packbf(sc[2 * kb + 1][2] * i2, sc[2 * kb + 1][3] * i2);
        #pragma unroll
        for (int dg = 0; dg < 4; dg++) {
            uint32_t vb[4];
            ldsm4t(vb, vsb + (kb * 16 + ((grp & 1) << 3) + lrow) * 144
                          + dg * 32 + ((grp >> 1) << 4));
            mma_bf16(acc[dg * 2],     pr, &vb[0]);
            mma_bf16(acc[dg * 2 + 1], pr, &vb[2]);
        }
    }
}

// ---------------- per-(src,head) attention (single-buffer, 8 CTAs/SM) -------
__global__ __launch_bounds__(128) void attn2(const __nv_bfloat16* __restrict__ qkv) {
    __shared__ __align__(16) __nv_bfloat16 Qs[64 * 72];
    __shared__ __align__(16) __nv_bfloat16 Ks[64 * 72];
    __shared__ __align__(16) __nv_bfloat16 Vs[64 * 72];

    int src = blockIdx.x >> 2;
    int h   = blockIdx.x & 3;
    int tid = threadIdx.x;
    int w = tid >> 5, lane = tid & 31;

    #pragma unroll
    for (int i = 0; i < 4; i++) {
        int t = tid + i * 128;
        int r = t >> 3, c = t & 7;
        *(uint4*)&Qs[r * 72 + c * 8] =
            *(const uint4*)(qkv + (size_t)(src * SS + r) * 768 + h * HDIM + c * 8);
    }
    __syncthreads();

    uint32_t qsb = (uint32_t)__cvta_generic_to_shared(Qs);
    uint32_t ksb = (uint32_t)__cvta_generic_to_shared(Ks);
    uint32_t vsb = (uint32_t)__cvta_generic_to_shared(Vs);

    int grp = lane >> 3, lrow = lane & 7;
    int rowA  = ((grp & 1) << 3) + lrow;
    int koffA = (grp >> 1) << 4;

    uint32_t qf[4][4];
    #pragma unroll
    for (int ds = 0; ds < 4; ds++)
        ldsm4(qf[ds], qsb + (16 * w + rowA) * 144 + ds * 32 + koffA);

    float acc[8][4];
    #pragma unroll
    for (int i = 0; i < 8; i++)
        #pragma unroll
        for (int v = 0; v < 4; v++) acc[i][v] = 0.0f;

    int q_len = g_len[src];
    bool act = (16 * w < q_len);
    int e0 = g_off[src], e1 = g_off[src + 1];

    for (int e = e0; e < e1; e++) {
        int dst = g_adj[e];
        int k_len = g_len[dst];
        int nkb = (k_len + 15) >> 4;          // 1..4
        int rup = nkb << 4;

        for (int t = tid; t < rup * 8; t += 128) {
            int r = t >> 3, c = t & 7;
            size_t base = (size_t)(dst * SS + r) * 768 + h * HDIM + c * 8;
            *(uint4*)&Ks[r * 72 + c * 8] = *(const uint4*)(qkv + base + 256);
            *(uint4*)&Vs[r * 72 + c * 8] = *(const uint4*)(qkv + base + 512);
        }
        __syncthreads();

        if (act) {
            switch (nkb) {
                case 1:  attn_edge<1>(ksb, vsb, qf, acc, k_len, lane); break;
                case 2:  attn_edge<2>(ksb, vsb, qf, acc, k_len, lane); break;
                case 3:  attn_edge<3>(ksb, vsb, qf, acc, k_len, lane); break;
                default: attn_edge<4>(ksb, vsb, qf, acc, k_len, lane); break;
            }
        }
        __syncthreads();
    }

    int r1 = 16 * w + (lane >> 2);
    int t2 = 2 * (lane & 3);
    #pragma unroll
    for (int dt = 0; dt < 8; dt++) {
        size_t b1 = (size_t)(src * SS + r1) * DD + h * HDIM + dt * 8 + t2;
        size_t b2 = (size_t)(src * SS + r1 + 8) * DD + h * HDIM + dt * 8 + t2;
        *(uint32_t*)(g_ctxb + b1) = packbf(acc[dt][0], acc[dt][1]);
        *(uint32_t*)(g_ctxb + b2) = packbf(acc[dt][2], acc[dt][3]);
    }
}

// ---------------- launcher ----------------
extern "C" void kernel_launch(void* const* d_in, const int* in_sizes, int n_in,
                              void* d_out, int out_size) {
    const float* nf = (const float*)d_in[0];
    const float* nm = (const float*)d_in[1];
    const float* lw = (const float*)d_in[2];
    const float* lb = (const float*)d_in[3];
    const float* wq = (const float*)d_in[4];
    const float* bq = (const float*)d_in[5];
    const float* wk = (const float*)d_in[6];
    const float* bk = (const float*)d_in[7];
    const float* wv = (const float*)d_in[8];
    const float* bv = (const float*)d_in[9];
    const float* wo = (const float*)d_in[10];
    const float* bo = (const float*)d_in[11];
    const int* ei32 = (const int*)d_in[13];
    float* out = (float*)d_out;

    __nv_bfloat16 *p_xnb, *p_qkvb, *p_ctxb, *p_wtb;
    float* p_bqkv;
    cudaGetSymbolAddress((void**)&p_xnb,  g_xnb);
    cudaGetSymbolAddress((void**)&p_qkvb, g_qkvb);
    cudaGetSymbolAddress((void**)&p_ctxb, g_ctxb);
    cudaGetSymbolAddress((void**)&p_wtb,  g_wtb);
    cudaGetSymbolAddress((void**)&p_bqkv, g_bqkv);

    static const int GEMM_SMEM = (128 + 64) * 264 * 2;  // 101376 B
    cudaFuncSetAttribute(gemm2, cudaFuncAttributeMaxDynamicSharedMemorySize, GEMM_SMEM);

    prep_kernel<<<9347, 256>>>(nf, lw, lb, nm, wq, wk, wv, wo, bq, bk, bv); // 1
    graph_kernel<<<1, 1024>>>(ei32);                                        // 2
    csr_scatter<<<EE / 256, 256>>>(ei32);                                   // 3

    dim3 gqkv(12, 512);                                                     // 4 (profiled)
    gemm2<<<gqkv, 256, GEMM_SMEM>>>(p_xnb, p_wtb, p_bqkv,
                                    p_qkvb, 768, nullptr, nullptr, nullptr);

    attn2<<<NN * HH, 128>>>(p_qkvb);                                        // 5

    dim3 go(4, 512);                                                        // 6
    gemm2<<<go, 256, GEMM_SMEM>>>(p_ctxb, p_wtb + 768 * DD, bo,
                                  nullptr, 0, out, nf, nm);
}